// round 3
// baseline (speedup 1.0000x reference)
#include <cuda_runtime.h>
#include <cstdint>

// Problem constants (fixed by the reference)
#define BB 2
#define LL 1024
#define MM 8
#define NN 16
#define CC 16
#define HH 64
#define WW 64
#define VOTES (MM * NN)            // 128
#define SLAB  (CC * HH * WW)       // 65536 floats = 256 KB per (b,l)
#define CGRP  2                    // channels per quantum
#define NGRP  (CC / CGRP)          // 8 quanta per slab
#define PLANE (HH * WW)            // 4096
#define QFLOATS (CGRP * PLANE)     // 8192 floats = 32 KB per quantum

// One CTA = one quantum = (slab bl, channel-group g). The entire quantum is
// built in a 32 KB smem histogram (zero + 256 smem atomics), then streamed to
// GMEM with evict-first .cs stores. DRAM traffic = pure 512 MB write stream:
// no global atomics, no RMW, no L2 read dependency.
__global__ __launch_bounds__(256, 6)
void ht_vote_kernel(const float* __restrict__ feats,   // [B,L,N,C]
                    const int*   __restrict__ vsrc,    // [B,L,2]
                    const int*   __restrict__ vdst,    // [B,L,2]
                    const int*   __restrict__ isrc,    // [B,L,M]
                    const int*   __restrict__ idst,    // [B,L,N]
                    float* __restrict__ out)           // [B,L,C,H,W]
{
    __shared__ float hist[QFLOATS];    // 32 KB: [CGRP][H*W]

    const int q  = blockIdx.x;         // 0 .. B*L*NGRP-1
    const int bl = q >> 3;             // NGRP == 8
    const int g  = q & 7;              // channel group
    const int b  = bl >> 10;           // LL == 1024
    const int t  = threadIdx.x;

    // ---- Gather chain (independent of smem zeroing; compiler interleaves,
    // so the 3 dependent L2 latencies hide under the zero loop).
    int   bin = -1;
    float w0 = 0.f, w1 = 0.f;
    if (t < VOTES) {
        const int m = t >> 4;          // NN == 16
        const int n = t & 15;

        const int s  = isrc[bl * MM + m];
        const int d  = idst[(b * LL + s) * NN + n];
        const int sy = vsrc[(b * LL + s) * 2 + 0];
        const int sx = vsrc[(b * LL + s) * 2 + 1];
        const int dy = vdst[(b * LL + d) * 2 + 0];
        const int dx = vdst[(b * LL + d) * 2 + 1];

        // voxels are int32: floor(float sub) == integer sub exactly
        const int by = dy - sy + HH / 2;
        const int bx = dx - sx + WW / 2;
        if (((unsigned)by < HH) & ((unsigned)bx < WW)) bin = by * WW + bx;

        // 2 channels of this vote's weight vector (8B, coalesced, L2-hot)
        const float2 w =
            ((const float2*)(feats + (((size_t)(b * LL + s)) * NN + n) * CC))[g];
        w0 = w.x; w1 = w.y;
    }

    // ---- Zero the smem histogram: 2048 float4 / 256 threads = 8 each ----
    {
        float4* h4 = (float4*)hist;
        const float4 z = make_float4(0.f, 0.f, 0.f, 0.f);
#pragma unroll
        for (int i = 0; i < QFLOATS / 4 / 256; i++)
            h4[t + i * 256] = z;
    }
    __syncthreads();

    // ---- Scatter: 128 votes x 2 channels = 256 smem atomics ----
    if (bin >= 0) {
        atomicAdd(&hist[bin], w0);
        atomicAdd(&hist[PLANE + bin], w1);
    }
    __syncthreads();

    // ---- Stream out: 32 KB smem -> GMEM, evict-first (never re-read) ----
    {
        float4* src = (float4*)hist;
        float4* dst = (float4*)(out + (size_t)bl * SLAB + g * QFLOATS);
#pragma unroll
        for (int i = 0; i < QFLOATS / 4 / 256; i++)
            __stcs(dst + t + i * 256, src[t + i * 256]);
    }
}

extern "C" void kernel_launch(void* const* d_in, const int* in_sizes, int n_in,
                              void* d_out, int out_size)
{
    const float* feats = (const float*)d_in[0];   // [B,L,N,C] f32
    const int*   vsrc  = (const int*)  d_in[1];   // [B,L,2]   i32
    const int*   vdst  = (const int*)  d_in[2];   // [B,L,2]   i32
    const int*   isrc  = (const int*)  d_in[3];   // [B,L,M]   i32
    const int*   idst  = (const int*)  d_in[4];   // [B,L,N]   i32
    float*       out   = (float*)d_out;           // [B,L,C,H,W] f32

    ht_vote_kernel<<<BB * LL * NGRP, 256>>>(feats, vsrc, vdst, isrc, idst, out);
}

// round 4
// speedup vs baseline: 1.0550x; 1.0550x over previous
#include <cuda_runtime.h>
#include <cstdint>

// Problem constants (fixed by the reference)
#define BB 2
#define LL 1024
#define MM 8
#define NN 16
#define CC 16
#define HH 64
#define WW 64
#define VOTES (MM * NN)            // 128
#define SLAB  (CC * HH * WW)       // 65536 floats = 256 KB per (b,l)
#define CGRP  4                    // channels per quantum
#define NGRP  (CC / CGRP)          // 4 quanta per slab
#define PLANE (HH * WW)            // 4096
#define QFLOATS (CGRP * PLANE)     // 16384 floats = 64 KB per quantum
#define NBMW   (QFLOATS / 32)      // 512 bitmap words
#define HSIZE  1024                // hash slots (load factor <= 0.5)

// Fibonacci hash of a position (0..16383) -> 10-bit slot
__device__ __forceinline__ unsigned hslot(int pos) {
    return ((unsigned)pos * 0x9E3779B1u) >> 22;
}

// One CTA = one quantum = (slab bl, channel-group g).
// Votes are collected into a sparse smem structure (bitmap + hash), then the
// 64 KB quantum is emitted as ONE pure write stream with vote values merged
// in registers. No global atomics, no RMW traffic, no second touch of lines.
__global__ __launch_bounds__(256, 6)
void ht_vote_kernel(const float* __restrict__ feats,   // [B,L,N,C]
                    const int*   __restrict__ vsrc,    // [B,L,2]
                    const int*   __restrict__ vdst,    // [B,L,2]
                    const int*   __restrict__ isrc,    // [B,L,M]
                    const int*   __restrict__ idst,    // [B,L,N]
                    float* __restrict__ out)           // [B,L,C,H,W]
{
    __shared__ unsigned bm[NBMW];      // 2 KB: one bit per output float
    __shared__ int      hkey[HSIZE];   // 4 KB
    __shared__ float    hval[HSIZE];   // 4 KB

    const int q  = blockIdx.x;         // 0 .. B*L*NGRP-1
    const int bl = q >> 2;             // NGRP == 4
    const int g  = q & 3;              // channel group
    const int b  = bl >> 10;           // LL == 1024
    const int t  = threadIdx.x;

    // ---- Gather chain (independent of smem init; latencies hide under it) ----
    int    bin = -1;
    float4 w   = make_float4(0.f, 0.f, 0.f, 0.f);
    if (t < VOTES) {
        const int m = t >> 4;          // NN == 16
        const int n = t & 15;

        const int s  = isrc[bl * MM + m];
        const int d  = idst[(b * LL + s) * NN + n];
        const int sy = vsrc[(b * LL + s) * 2 + 0];
        const int sx = vsrc[(b * LL + s) * 2 + 1];
        const int dy = vdst[(b * LL + d) * 2 + 0];
        const int dx = vdst[(b * LL + d) * 2 + 1];

        // voxels are int32: floor(float sub) == integer sub exactly
        const int by = dy - sy + HH / 2;
        const int bx = dx - sx + WW / 2;
        if (((unsigned)by < HH) & ((unsigned)bx < WW)) bin = by * WW + bx;

        // 4 channels of this vote's weight vector (16B, coalesced, L2-hot)
        w = ((const float4*)(feats + (((size_t)(b * LL + s)) * NN + n) * CC))[g];
    }

    // ---- Init sparse structures (2560 words / 256 threads = 10 each) ----
#pragma unroll
    for (int i = 0; i < NBMW / 256; i++)  bm[t + i * 256] = 0u;
#pragma unroll
    for (int i = 0; i < HSIZE / 256; i++) {
        hkey[t + i * 256] = -1;
        hval[t + i * 256] = 0.f;
    }
    __syncthreads();

    // ---- Insert: each vote thread registers its 4 (channel,bin) items ----
    if (bin >= 0) {
#pragma unroll
        for (int c = 0; c < CGRP; c++) {
            const int   pos = c * PLANE + bin;
            const float wv  = (&w.x)[c];
            unsigned h = hslot(pos);
            for (;;) {
                const int prev = atomicCAS(&hkey[h], -1, pos);
                if (prev == -1 || prev == pos) { atomicAdd(&hval[h], wv); break; }
                h = (h + 1) & (HSIZE - 1);
            }
            atomicOr(&bm[pos >> 5], 1u << (pos & 31));
        }
    }
    __syncthreads();

    // ---- Emit: one pure 64 KB write stream, votes merged in registers ----
    {
        float4* dst = (float4*)(out + (size_t)bl * SLAB + g * QFLOATS);
#pragma unroll
        for (int i = 0; i < QFLOATS / 4 / 256; i++) {   // 16 per thread
            const int j = t + i * 256;                  // float4 index
            const unsigned nib = (bm[j >> 3] >> ((j & 7) * 4)) & 0xFu;
            float4 v = make_float4(0.f, 0.f, 0.f, 0.f);
            if (nib) {                                  // ~3% of float4s
                const int p0 = 4 * j;
#pragma unroll
                for (int c = 0; c < 4; c++) {
                    if (nib & (1u << c)) {
                        const int pos = p0 + c;
                        unsigned h = hslot(pos);
                        while (hkey[h] != pos) h = (h + 1) & (HSIZE - 1);
                        (&v.x)[c] = hval[h];
                    }
                }
            }
            __stcs(dst + j, v);                         // evict-first: never re-read
        }
    }
}

extern "C" void kernel_launch(void* const* d_in, const int* in_sizes, int n_in,
                              void* d_out, int out_size)
{
    const float* feats = (const float*)d_in[0];   // [B,L,N,C] f32
    const int*   vsrc  = (const int*)  d_in[1];   // [B,L,2]   i32
    const int*   vdst  = (const int*)  d_in[2];   // [B,L,2]   i32
    const int*   isrc  = (const int*)  d_in[3];   // [B,L,M]   i32
    const int*   idst  = (const int*)  d_in[4];   // [B,L,N]   i32
    float*       out   = (float*)d_out;           // [B,L,C,H,W] f32

    ht_vote_kernel<<<BB * LL * NGRP, 256>>>(feats, vsrc, vdst, isrc, idst, out);
}